// round 4
// baseline (speedup 1.0000x reference)
#include <cuda_runtime.h>

#define T_DATA 20000
#define E_NO   2000
#define I_NO   500
#define SUB    12
#define CTAP   40            // tail beyond lag 40 < 2e-5 of syn value
#define TT     320           // timesteps per block
#define NBLK   63            // ceil(20000/320)
#define INLEN  384           // staged IN length; i -> t = t0 - 52 + i
#define INOFF  52            // 13 + (CTAP-1)
#define SYNLEN 336           // syn j -> t = t0 - 13 + j, j in [0,333)
#define NTHR   512

#define FMA2(d,a,b,c) asm("fma.rn.f32x2 %0, %1, %2, %3;" : "=l"(d) : "l"(a), "l"(b), "l"(c))
#define PACK2(o,lo,hi) asm("mov.b64 %0, {%1, %2};" : "=l"(o) : "f"(lo), "f"(hi))
#define UNPK2(lo,hi,i) asm("mov.b64 {%0, %1}, %2;" : "=f"(lo), "=f"(hi) : "l"(i))

__device__ __forceinline__ float sigm(float x) { return 1.f / (1.f + __expf(-x)); }

// smem layout (bytes):
//   kp   @ 0      : float2[SUB][2][CTAP] = 7680   ((s-kern, ns-kern) coeff pairs)
//   sme  @ 7680   : unsigned[64][13]     = 3328
//   smi  @ 11008  : unsigned[16][13]     = 832
//   inbe @ 11840  : float[SUB][INLEN]    = 18432
//   inbi @ 30272  : float[SUB][INLEN]    = 18432
//   shs  @ 48704  : float[SUB][SYNLEN]   = 16128
//   shn  @ 64832  : float[SUB][SYNLEN]   = 16128
//   cw   @ 80960  : float[144], cd @ 81536: float[144]
//   ths/thn/wsb/wnb @ 82112.. : 4 x 12 floats  -> total 82304
#define SMEM_BYTES 82304

__global__ __launch_bounds__(NTHR, 1) void k_all(
    const float* __restrict__ Se, const float* __restrict__ Si,
    const float* __restrict__ Ce, const float* __restrict__ Ci,
    const float* __restrict__ C_den,
    const float* __restrict__ Ws_syn, const float* __restrict__ Wns_syn,
    const float* __restrict__ Ds, const float* __restrict__ Dns,
    const float* __restrict__ Ths_g, const float* __restrict__ Thns_g,
    const float* __restrict__ Ws_g, const float* __restrict__ Wns_g,
    float* __restrict__ out)
{
    extern __shared__ __align__(16) char dyn[];
    float2*   kp   = (float2*)dyn;
    unsigned* sme  = (unsigned*)(dyn + 7680);
    unsigned* smi  = (unsigned*)(dyn + 11008);
    float*    inbe = (float*)(dyn + 11840);
    float*    inbi = (float*)(dyn + 30272);
    float*    shs  = (float*)(dyn + 48704);
    float*    shn  = (float*)(dyn + 64832);
    float*    cw   = (float*)(dyn + 80960);
    float*    cd   = (float*)(dyn + 81536);
    float*    ths  = (float*)(dyn + 82112);
    float*    thn  = (float*)(dyn + 82160);
    float*    wsb  = (float*)(dyn + 82208);
    float*    wnb  = (float*)(dyn + 82256);

    const int tid = threadIdx.x;
    const int warp = tid >> 5, lane = tid & 31;
    const int t0 = blockIdx.x * TT;

    // ---- phase 0a: connectivity masks via warp ballots (L2-cached C reads) ----
    for (int W = warp; W < 960; W += 16) {
        if (W < 768) {
            int s = W >> 6, m = W & 63, it = m >> 2, c = m & 3;
            int e = it * 128 + lane * 4 + c;
            bool b = (e < E_NO) && (Ce[s * E_NO + e] != 0.f);
            unsigned bits = __ballot_sync(0xffffffffu, b);
            if (lane == 0) sme[m * 13 + s] = bits;
        } else {
            int jj = W - 768;
            int s = jj >> 4, m = jj & 15, it = m >> 2, c = m & 3;
            int e = it * 128 + lane * 4 + c;
            bool b = (e < I_NO) && (Ci[s * I_NO + e] != 0.f);
            unsigned bits = __ballot_sync(0xffffffffu, b);
            if (lane == 0) smi[m * 13 + s] = bits;
        }
    }
    // ---- phase 0b: reversed kernel coefficient pairs (s, ns) ----
    for (int id = tid; id < SUB * 2 * CTAP; id += NTHR) {
        int s = id / (2 * CTAP), rem = id % (2 * CTAP), ch = rem / CTAP, m = rem % CTAP;
        float fk = (float)(CTAP - 1 - m);
        float vs, vn;
        {
            float u = fmaxf(fk - expf(Ds[s * 2 + ch]), 0.f);
            float a = u, b = u * 0.60653065971f, c = u * 0.36787944117f;
            vs = Ws_syn[s * 6 + ch] * a * expf(-a) + Ws_syn[s * 6 + 2 + ch] * b * expf(-b) +
                 Ws_syn[s * 6 + 4 + ch] * c * expf(-c);
        }
        {
            float u = fmaxf(fk - expf(Dns[s * 2 + ch]), 0.f);
            float a = u, b = u * 0.60653065971f, c = u * 0.36787944117f;
            vn = Wns_syn[s * 6 + ch] * a * expf(-a) + Wns_syn[s * 6 + 2 + ch] * b * expf(-b) +
                 Wns_syn[s * 6 + 4 + ch] * c * expf(-c);
        }
        kp[id] = make_float2(vs, vn);
    }
    if (tid < SUB * SUB) {
        float c = C_den[tid];
        cd[tid] = c;
        cw[tid] = c * Wns_g[tid % SUB];
    }
    if (tid < SUB) {
        ths[tid] = Ths_g[tid];
        thn[tid] = Thns_g[tid];
        wsb[tid] = Ws_g[tid];
        wnb[tid] = Wns_g[tid];
    }
    __syncthreads();

    // ---- phase 1: IN rows (incl. halo) via ballot + popcount, HBM-bound ----
    for (int k = 0; k < 24; k++) {
        int idx = warp * 24 + k;                 // 16 warps x 24 = 384
        int g = t0 - INOFF + idx;
        bool valid = (g >= 0 && g < T_DATA);
        const float* re = Se + (size_t)(valid ? g : 0) * E_NO;
        const float* ri = Si + (size_t)(valid ? g : 0) * I_NO;
        int acc_e = 0, acc_i = 0;
#pragma unroll
        for (int ob = 0; ob < 2; ob++) {
            float4 v[8];
#pragma unroll
            for (int q = 0; q < 8; q++) {
                int base = (ob * 8 + q) * 128 + lane * 4;
                v[q] = (valid && base < E_NO) ? *(const float4*)(re + base)
                                              : make_float4(0.f, 0.f, 0.f, 0.f);
            }
#pragma unroll
            for (int q = 0; q < 8; q++) {
                int it = ob * 8 + q;
                unsigned m0 = __ballot_sync(0xffffffffu, v[q].x != 0.f);
                unsigned m1 = __ballot_sync(0xffffffffu, v[q].y != 0.f);
                unsigned m2 = __ballot_sync(0xffffffffu, v[q].z != 0.f);
                unsigned m3 = __ballot_sync(0xffffffffu, v[q].w != 0.f);
                if (lane < SUB) {
                    acc_e += __popc(m0 & sme[(it * 4 + 0) * 13 + lane]);
                    acc_e += __popc(m1 & sme[(it * 4 + 1) * 13 + lane]);
                    acc_e += __popc(m2 & sme[(it * 4 + 2) * 13 + lane]);
                    acc_e += __popc(m3 & sme[(it * 4 + 3) * 13 + lane]);
                }
            }
        }
        {
            float4 v[4];
#pragma unroll
            for (int q = 0; q < 4; q++) {
                int base = q * 128 + lane * 4;
                v[q] = (valid && base < I_NO) ? *(const float4*)(ri + base)
                                              : make_float4(0.f, 0.f, 0.f, 0.f);
            }
#pragma unroll
            for (int q = 0; q < 4; q++) {
                unsigned m0 = __ballot_sync(0xffffffffu, v[q].x != 0.f);
                unsigned m1 = __ballot_sync(0xffffffffu, v[q].y != 0.f);
                unsigned m2 = __ballot_sync(0xffffffffu, v[q].z != 0.f);
                unsigned m3 = __ballot_sync(0xffffffffu, v[q].w != 0.f);
                if (lane < SUB) {
                    acc_i += __popc(m0 & smi[(q * 4 + 0) * 13 + lane]);
                    acc_i += __popc(m1 & smi[(q * 4 + 1) * 13 + lane]);
                    acc_i += __popc(m2 & smi[(q * 4 + 2) * 13 + lane]);
                    acc_i += __popc(m3 & smi[(q * 4 + 3) * 13 + lane]);
                }
            }
        }
        if (lane < SUB) {
            inbe[lane * INLEN + idx] = (float)acc_e;
            inbi[lane * INLEN + idx] = (float)acc_i;
        }
    }
    __syncthreads();

    // ---- phase 2: causal conv, packed f32x2 (s,ns) pairs, 4 outputs/thread ----
    const unsigned long long* kpu = (const unsigned long long*)kp;
#pragma unroll 1
    for (int half = 0; half < 2; half++) {
        int id = tid + half * NTHR;
        if (id < SUB * 84) {                       // 84 groups of 4 -> 336 outputs
            int s = id / 84, g = id % 84, j0 = g * 4;
            const float4* re4 = (const float4*)(inbe + s * INLEN);
            const float4* ri4 = (const float4*)(inbi + s * INLEN);
            const unsigned long long* kpe = kpu + (s * 2 + 0) * CTAP;
            const unsigned long long* kpi = kpu + (s * 2 + 1) * CTAP;
            unsigned long long acc[4] = {0ull, 0ull, 0ull, 0ull};
            float4 Ae = re4[g], Be = re4[g + 1];
            float4 Ai = ri4[g], Bi = ri4[g + 1];
#pragma unroll
            for (int kb = 0; kb < CTAP; kb += 4) {
                float4 Ce4 = re4[g + kb / 4 + 2];   // max idx g+11 <= 94 < 96
                float4 Ci4 = ri4[g + kb / 4 + 2];
                float we[8] = {Ae.x, Ae.y, Ae.z, Ae.w, Be.x, Be.y, Be.z, Be.w};
                float wi[8] = {Ai.x, Ai.y, Ai.z, Ai.w, Bi.x, Bi.y, Bi.z, Bi.w};
                unsigned long long Ep[7], Ip[7];
#pragma unroll
                for (int x = 0; x < 7; x++) {
                    PACK2(Ep[x], we[x], we[x]);
                    PACK2(Ip[x], wi[x], wi[x]);
                }
#pragma unroll
                for (int u = 0; u < 4; u++) {
                    unsigned long long pe = kpe[kb + u], pi = kpi[kb + u];
#pragma unroll
                    for (int r = 0; r < 4; r++) {
                        FMA2(acc[r], pe, Ep[u + r], acc[r]);
                        FMA2(acc[r], pi, Ip[u + r], acc[r]);
                    }
                }
                Ae = Be; Be = Ce4; Ai = Bi; Bi = Ci4;
            }
#pragma unroll
            for (int r = 0; r < 4; r++) {
                float lo, hi;
                UNPK2(lo, hi, acc[r]);
                shs[s * SYNLEN + j0 + r] = lo;
                shn[s * SYNLEN + j0 + r] = hi;
            }
        }
    }
    __syncthreads();

    // ---- phase 3: warp-shuffle wavefront recurrence + direct output stores ----
    {
        const int t = t0 + warp * 20 + lane - 12;    // 16 warps x 20 outputs
        const int j = warp * 20 + lane + 1;          // syn index for time t
        const bool tin = (t >= 0);
        const bool rec = (t >= 1);

        float sn[SUB], ss[SUB];
#pragma unroll
        for (int q = 0; q < SUB; q++) {
            sn[q] = tin ? shn[q * SYNLEN + j] : 0.f;
            ss[q] = tin ? shs[q * SYNLEN + j] : 0.f;
        }
        float ssp0 = rec ? shs[j - 1] : 0.f;

        float sig[SUB], sigp[SUB];
#pragma unroll
        for (int q = 0; q < SUB; q++) {
            float r = 0.f;
#pragma unroll
            for (int qq = 0; qq < q; qq++) r += cw[q * SUB + qq] * sigp[qq];
            float x = sn[q] + thn[q] + (rec ? r : 0.f);
            sig[q] = sigm(x);
            sigp[q] = __shfl_up_sync(0xffffffffu, sig[q], 1);
        }

        if (lane >= 12 && t < T_DATA) {
            float* o = out + (size_t)t * (3 * SUB - 1);
            o[0] = sigm(ss[0] + ths[0]) * wsb[0];
#pragma unroll
            for (int q = 1; q < SUB; q++) o[q] = sig[q] * wsb[q];
#pragma unroll
            for (int q = 0; q < SUB; q++) o[SUB + q] = sig[q] * wnb[q];

            float ysp[SUB];
            ysp[0] = rec ? sigm(ssp0 + ths[0]) * wsb[0] : 0.f;
#pragma unroll
            for (int q = 1; q < SUB; q++) ysp[q] = rec ? sigp[q] * wsb[q] : 0.f;
#pragma unroll
            for (int i = 1; i < SUB; i++) {
                float x = ss[i] + ths[i];
#pragma unroll
                for (int qq = 0; qq < i; qq++) x = fmaf(cd[i * SUB + qq], ysp[qq], x);
                o[2 * SUB + (i - 1)] = sigm(x);
            }
        }
    }
}

// ---------------- launcher ----------------
extern "C" void kernel_launch(void* const* d_in, const int* in_sizes, int n_in,
                              void* d_out, int out_size) {
    const float* S_e      = (const float*)d_in[0];
    const float* S_i      = (const float*)d_in[1];
    const float* C_syn_e  = (const float*)d_in[2];
    const float* C_syn_i  = (const float*)d_in[3];
    const float* C_den    = (const float*)d_in[4];
    const float* W_s_syn  = (const float*)d_in[5];
    const float* W_ns_syn = (const float*)d_in[6];
    const float* Delta_s  = (const float*)d_in[7];
    const float* Delta_ns = (const float*)d_in[8];
    const float* Theta_s  = (const float*)d_in[9];
    const float* Theta_ns = (const float*)d_in[10];
    const float* W_s_sub  = (const float*)d_in[11];
    const float* W_ns_sub = (const float*)d_in[12];
    float* out = (float*)d_out;

    cudaFuncSetAttribute(k_all, cudaFuncAttributeMaxDynamicSharedMemorySize, SMEM_BYTES);
    k_all<<<NBLK, NTHR, SMEM_BYTES>>>(S_e, S_i, C_syn_e, C_syn_i, C_den,
                                      W_s_syn, W_ns_syn, Delta_s, Delta_ns,
                                      Theta_s, Theta_ns, W_s_sub, W_ns_sub, out);
}

// round 6
// speedup vs baseline: 1.9226x; 1.9226x over previous
#include <cuda_runtime.h>

#define T_DATA 20000
#define E_NO   2000
#define I_NO   500
#define SUB    12
#define CTAP   40            // tail beyond lag 40 contributes < 3e-6 rel
#define TT     80            // fused outputs per block
#define INLEN  144           // staged IN length; i -> t = t0 - 52 + i (136 real, pad 144)
#define SYNLEN 96            // syn j -> t = t0 - 13 + j

__device__ unsigned g_mask_e[SUB][64];
__device__ unsigned g_mask_i[SUB][16];
__device__ float g_INe[SUB][T_DATA];
__device__ float g_INi[SUB][T_DATA];

__device__ __forceinline__ float sigm(float x) { return 1.f / (1.f + __expf(-x)); }

// ---------------- K0: pack connectivity into bitmasks (grid-stride warp tasks) -----
__global__ __launch_bounds__(256) void k_pack(const float* __restrict__ Ce,
                                              const float* __restrict__ Ci) {
    int lane = threadIdx.x & 31;
    int warp0 = (blockIdx.x * blockDim.x + threadIdx.x) >> 5;
    int nwarps = (gridDim.x * blockDim.x) >> 5;
    for (int w = warp0; w < SUB * 64 + SUB * 16; w += nwarps) {
        if (w < SUB * 64) {
            int s = w >> 6, m = w & 63;
            int it = m >> 2, c = m & 3;
            int e = it * 128 + lane * 4 + c;
            bool b = (e < E_NO) && (Ce[s * E_NO + e] != 0.f);
            unsigned bits = __ballot_sync(0xffffffffu, b);
            if (lane == 0) g_mask_e[s][m] = bits;
        } else {
            int j = w - SUB * 64;
            int s = j >> 4, m = j & 15;
            int it = m >> 2, c = m & 3;
            int e = it * 128 + lane * 4 + c;
            bool b = (e < I_NO) && (Ci[s * I_NO + e] != 0.f);
            unsigned bits = __ballot_sync(0xffffffffu, b);
            if (lane == 0) g_mask_i[s][m] = bits;
        }
    }
}

// ---------------- K1: IN = S @ C.T, 512 thr/block, deep load batches ---------------
__global__ __launch_bounds__(512) void k_reduce(const float* __restrict__ Se,
                                                const float* __restrict__ Si) {
    __shared__ unsigned long long sme2[32][13];
    __shared__ unsigned long long smi2[8][13];
    for (int i = threadIdx.x; i < SUB * 32; i += blockDim.x) {
        int s = i >> 5, p = i & 31;
        sme2[p][s] = (unsigned long long)g_mask_e[s][2 * p] |
                     ((unsigned long long)g_mask_e[s][2 * p + 1] << 32);
    }
    for (int i = threadIdx.x; i < SUB * 8; i += blockDim.x) {
        int s = i >> 3, p = i & 7;
        smi2[p][s] = (unsigned long long)g_mask_i[s][2 * p] |
                     ((unsigned long long)g_mask_i[s][2 * p + 1] << 32);
    }
    __syncthreads();

    int warp = threadIdx.x >> 5, lane = threadIdx.x & 31;
    int row = blockIdx.x * 16 + warp;
    if (row >= T_DATA) return;

    const float* re = Se + (size_t)row * E_NO;
    const float* ri = Si + (size_t)row * I_NO;
    int acc_e = 0, acc_i = 0;

#pragma unroll
    for (int ob = 0; ob < 2; ob++) {
        float4 v[8];
#pragma unroll
        for (int q = 0; q < 8; q++) {
            int base = (ob * 8 + q) * 128 + lane * 4;
            v[q] = (base < E_NO) ? *(const float4*)(re + base)
                                 : make_float4(0.f, 0.f, 0.f, 0.f);
        }
#pragma unroll
        for (int q = 0; q < 8; q++) {
            int it = ob * 8 + q;
            unsigned m0 = __ballot_sync(0xffffffffu, v[q].x != 0.f);
            unsigned m1 = __ballot_sync(0xffffffffu, v[q].y != 0.f);
            unsigned m2 = __ballot_sync(0xffffffffu, v[q].z != 0.f);
            unsigned m3 = __ballot_sync(0xffffffffu, v[q].w != 0.f);
            if (lane < SUB) {
                unsigned long long A = (unsigned long long)m0 | ((unsigned long long)m1 << 32);
                unsigned long long B = (unsigned long long)m2 | ((unsigned long long)m3 << 32);
                acc_e += __popcll(A & sme2[it * 2 + 0][lane]);
                acc_e += __popcll(B & sme2[it * 2 + 1][lane]);
            }
        }
    }
    {
        float4 v[4];
#pragma unroll
        for (int q = 0; q < 4; q++) {
            int base = q * 128 + lane * 4;
            v[q] = (base < I_NO) ? *(const float4*)(ri + base)
                                 : make_float4(0.f, 0.f, 0.f, 0.f);
        }
#pragma unroll
        for (int q = 0; q < 4; q++) {
            unsigned m0 = __ballot_sync(0xffffffffu, v[q].x != 0.f);
            unsigned m1 = __ballot_sync(0xffffffffu, v[q].y != 0.f);
            unsigned m2 = __ballot_sync(0xffffffffu, v[q].z != 0.f);
            unsigned m3 = __ballot_sync(0xffffffffu, v[q].w != 0.f);
            if (lane < SUB) {
                unsigned long long A = (unsigned long long)m0 | ((unsigned long long)m1 << 32);
                unsigned long long B = (unsigned long long)m2 | ((unsigned long long)m3 << 32);
                acc_i += __popcll(A & smi2[q * 2 + 0][lane]);
                acc_i += __popcll(B & smi2[q * 2 + 1][lane]);
            }
        }
    }
    if (lane < SUB) {
        g_INe[lane][row] = (float)acc_e;
        g_INi[lane][row] = (float)acc_i;
    }
}

// ---------------- K2: fused conv(40 taps) + wavefront recurrence, TT=80 ------------
__global__ __launch_bounds__(288) void k_fused(const float* __restrict__ Ws_syn,
                                               const float* __restrict__ Wns_syn,
                                               const float* __restrict__ Ds,
                                               const float* __restrict__ Dns,
                                               const float* __restrict__ C_den,
                                               const float* __restrict__ Ths_g,
                                               const float* __restrict__ Thns_g,
                                               const float* __restrict__ Ws_g,
                                               const float* __restrict__ Wns_g,
                                               float* __restrict__ out) {
    __shared__ float ker[SUB][4][CTAP];                  // [s][e_s,i_s,e_ns,i_ns][m]
    __shared__ __align__(16) float inbe[SUB][INLEN];
    __shared__ __align__(16) float inbi[SUB][INLEN];
    __shared__ float shs[SUB][SYNLEN], shn[SUB][SYNLEN];
    __shared__ float cw[SUB][SUB], cd[SUB][SUB];
    __shared__ float ths[SUB], thn[SUB], wsb[SUB], wnb[SUB];

    const int tid = threadIdx.x;
    const int warp = tid >> 5, lane = tid & 31;
    const int t0 = blockIdx.x * TT;

    // kernel coefficients: 12*4*40 = 1920 entries
    for (int id = tid; id < SUB * 4 * CTAP; id += 288) {
        int s = id / (4 * CTAP), rem = id % (4 * CTAP);
        int c = rem / CTAP, m = rem % CTAP;
        int ch = c & 1;
        const float* W = (c >= 2) ? Wns_syn : Ws_syn;
        const float* D = (c >= 2) ? Dns : Ds;
        float fk = (float)(CTAP - 1 - m);                // reversed: index m = lag CTAP-1-m
        float u = fmaxf(fk - expf(D[s * 2 + ch]), 0.f);
        float a = u, b = u * 0.60653065971f, cc = u * 0.36787944117f;
        ker[s][c][m] = W[s * 6 + ch] * a * expf(-a) + W[s * 6 + 2 + ch] * b * expf(-b) +
                       W[s * 6 + 4 + ch] * cc * expf(-cc);
    }
    if (tid < SUB * SUB) {
        float c = C_den[tid];
        cd[tid / SUB][tid % SUB] = c;
        cw[tid / SUB][tid % SUB] = c * Wns_g[tid % SUB];
    }
    if (tid < SUB) {
        ths[tid] = Ths_g[tid];
        thn[tid] = Thns_g[tid];
        wsb[tid] = Ws_g[tid];
        wnb[tid] = Wns_g[tid];
    }
    // stage IN: i in [0,144) -> t = t0 - 52 + i (zero-fill OOB and pad)
    for (int i = tid; i < SUB * INLEN; i += 288) {
        int s = i / INLEN, ii = i % INLEN;
        int g = t0 - 52 + ii;
        bool in = (g >= 0 && g < T_DATA && ii < 136);
        inbe[s][ii] = in ? g_INe[s][g] : 0.f;
        inbi[s][ii] = in ? g_INi[s][g] : 0.f;
    }
    __syncthreads();

    // conv: 288 threads = 12 subs x 24 groups of 4 outputs; syn[j] = sum_m ker[m]*IN[j+m]
    {
        int s = tid / 24, g = tid % 24;
        const float4* re4 = (const float4*)inbe[s];
        const float4* ri4 = (const float4*)inbi[s];
        const float* kes = ker[s][0];
        const float* kis = ker[s][1];
        const float* ken = ker[s][2];
        const float* kin = ker[s][3];

        float accs[4] = {0, 0, 0, 0}, accn[4] = {0, 0, 0, 0};
        float4 Ae = re4[g], Be = re4[g + 1];
        float4 Ai = ri4[g], Bi = ri4[g + 1];
#pragma unroll
        for (int kb = 0; kb < CTAP; kb += 4) {
            float4 Ce4 = re4[g + kb / 4 + 2];
            float4 Ci4 = ri4[g + kb / 4 + 2];
            float we[8] = {Ae.x, Ae.y, Ae.z, Ae.w, Be.x, Be.y, Be.z, Be.w};
            float wi[8] = {Ai.x, Ai.y, Ai.z, Ai.w, Bi.x, Bi.y, Bi.z, Bi.w};
#pragma unroll
            for (int u = 0; u < 4; u++) {
                float c0 = kes[kb + u], c1 = kis[kb + u];
                float c2 = ken[kb + u], c3 = kin[kb + u];
#pragma unroll
                for (int r = 0; r < 4; r++) {
                    float e = we[u + r], i2 = wi[u + r];
                    accs[r] = fmaf(c0, e, accs[r]);
                    accs[r] = fmaf(c1, i2, accs[r]);
                    accn[r] = fmaf(c2, e, accn[r]);
                    accn[r] = fmaf(c3, i2, accn[r]);
                }
            }
            Ae = Be; Be = Ce4; Ai = Bi; Bi = Ci4;
        }
        int j0 = g * 4;
#pragma unroll
        for (int r = 0; r < 4; r++) {
            shs[s][j0 + r] = accs[r];
            shn[s][j0 + r] = accn[r];
        }
    }
    __syncthreads();

    // recurrence: warps 0..3 cover 80 outputs (20 each, 12-lane halo)
    if (warp < 4) {
        const int t = t0 + warp * 20 + lane - 12;
        const int j = warp * 20 + lane + 1;
        const bool tin = (t >= 0);
        const bool rec = (t >= 1);

        float sn[SUB], ss[SUB];
#pragma unroll
        for (int q = 0; q < SUB; q++) {
            sn[q] = tin ? shn[q][j] : 0.f;
            ss[q] = tin ? shs[q][j] : 0.f;
        }
        float ssp0 = rec ? shs[0][j - 1] : 0.f;

        float sig[SUB], sigp[SUB];
#pragma unroll
        for (int q = 0; q < SUB; q++) {
            float r = 0.f;
#pragma unroll
            for (int qq = 0; qq < q; qq++) r += cw[q][qq] * sigp[qq];
            float x = sn[q] + thn[q] + (rec ? r : 0.f);
            sig[q] = sigm(x);
            sigp[q] = __shfl_up_sync(0xffffffffu, sig[q], 1);
        }

        if (lane >= 12 && t < T_DATA) {
            float* o = out + (size_t)t * (3 * SUB - 1);
            o[0] = sigm(ss[0] + ths[0]) * wsb[0];
#pragma unroll
            for (int q = 1; q < SUB; q++) o[q] = sig[q] * wsb[q];
#pragma unroll
            for (int q = 0; q < SUB; q++) o[SUB + q] = sig[q] * wnb[q];

            float ysp[SUB];
            ysp[0] = rec ? sigm(ssp0 + ths[0]) * wsb[0] : 0.f;
#pragma unroll
            for (int q = 1; q < SUB; q++) ysp[q] = rec ? sigp[q] * wsb[q] : 0.f;
#pragma unroll
            for (int i = 1; i < SUB; i++) {
                float x = ss[i] + ths[i];
#pragma unroll
                for (int qq = 0; qq < i; qq++) x = fmaf(cd[i][qq], ysp[qq], x);
                o[2 * SUB + (i - 1)] = sigm(x);
            }
        }
    }
}

// ---------------- launcher ----------------
extern "C" void kernel_launch(void* const* d_in, const int* in_sizes, int n_in,
                              void* d_out, int out_size) {
    const float* S_e      = (const float*)d_in[0];
    const float* S_i      = (const float*)d_in[1];
    const float* C_syn_e  = (const float*)d_in[2];
    const float* C_syn_i  = (const float*)d_in[3];
    const float* C_den    = (const float*)d_in[4];
    const float* W_s_syn  = (const float*)d_in[5];
    const float* W_ns_syn = (const float*)d_in[6];
    const float* Delta_s  = (const float*)d_in[7];
    const float* Delta_ns = (const float*)d_in[8];
    const float* Theta_s  = (const float*)d_in[9];
    const float* Theta_ns = (const float*)d_in[10];
    const float* W_s_sub  = (const float*)d_in[11];
    const float* W_ns_sub = (const float*)d_in[12];
    float* out = (float*)d_out;

    k_pack<<<30, 256>>>(C_syn_e, C_syn_i);
    k_reduce<<<1250, 512>>>(S_e, S_i);
    k_fused<<<250, 288>>>(W_s_syn, W_ns_syn, Delta_s, Delta_ns,
                          C_den, Theta_s, Theta_ns, W_s_sub, W_ns_sub, out);
}

// round 7
// speedup vs baseline: 1.9988x; 1.0396x over previous
#include <cuda_runtime.h>

#define T_DATA 20000
#define E_NO   2000
#define I_NO   500
#define SUB    12
#define CTAP   40            // tail beyond lag 40 contributes < 3e-6 rel
#define TT     80            // fused outputs per block
#define INLEN  144           // staged IN length; i -> t = t0 - 52 + i (136 real, pad 144)
#define SYNLEN 96            // syn j -> t = t0 - 13 + j

__device__ unsigned g_mask_e[SUB][64];
__device__ unsigned g_mask_i[SUB][16];
__device__ float g_INe[SUB][T_DATA];
__device__ float g_INi[SUB][T_DATA];

__device__ __forceinline__ float sigm(float x) { return 1.f / (1.f + __expf(-x)); }

// ---------------- K0: pack connectivity; 1 warp = 1 coalesced 512B chunk -> 4 words
// chunk (s, it): lane l loads float4 at elem it*128 + l*4; component c is bit l of
// word m = it*4 + c  (bit l <-> element it*128 + l*4 + c, matching k_reduce's use).
__global__ __launch_bounds__(128) void k_pack(const float* __restrict__ Ce,
                                              const float* __restrict__ Ci) {
    int gw = (blockIdx.x * blockDim.x + threadIdx.x) >> 5;   // 240 warps
    int lane = threadIdx.x & 31;
    if (gw < SUB * 16) {                                     // e-chunks: 12 subs x 16
        int s = gw >> 4, it = gw & 15;
        int base = it * 128 + lane * 4;
        float4 v = (base < E_NO) ? *(const float4*)(Ce + s * E_NO + base)
                                 : make_float4(0.f, 0.f, 0.f, 0.f);
        unsigned m0 = __ballot_sync(0xffffffffu, v.x != 0.f);
        unsigned m1 = __ballot_sync(0xffffffffu, v.y != 0.f);
        unsigned m2 = __ballot_sync(0xffffffffu, v.z != 0.f);
        unsigned m3 = __ballot_sync(0xffffffffu, v.w != 0.f);
        if (lane == 0) {
            g_mask_e[s][it * 4 + 0] = m0;
            g_mask_e[s][it * 4 + 1] = m1;
            g_mask_e[s][it * 4 + 2] = m2;
            g_mask_e[s][it * 4 + 3] = m3;
        }
    } else if (gw < SUB * 16 + SUB * 4) {                    // i-chunks: 12 subs x 4
        int j = gw - SUB * 16;
        int s = j >> 2, it = j & 3;
        int base = it * 128 + lane * 4;
        float4 v = (base < I_NO) ? *(const float4*)(Ci + s * I_NO + base)
                                 : make_float4(0.f, 0.f, 0.f, 0.f);
        unsigned m0 = __ballot_sync(0xffffffffu, v.x != 0.f);
        unsigned m1 = __ballot_sync(0xffffffffu, v.y != 0.f);
        unsigned m2 = __ballot_sync(0xffffffffu, v.z != 0.f);
        unsigned m3 = __ballot_sync(0xffffffffu, v.w != 0.f);
        if (lane == 0) {
            g_mask_i[s][it * 4 + 0] = m0;
            g_mask_i[s][it * 4 + 1] = m1;
            g_mask_i[s][it * 4 + 2] = m2;
            g_mask_i[s][it * 4 + 3] = m3;
        }
    }
}

// ---------------- K1: IN = S @ C.T, 512 thr/block, deep load batches ---------------
__global__ __launch_bounds__(512) void k_reduce(const float* __restrict__ Se,
                                                const float* __restrict__ Si) {
    __shared__ unsigned long long sme2[32][13];
    __shared__ unsigned long long smi2[8][13];
    for (int i = threadIdx.x; i < SUB * 32; i += blockDim.x) {
        int s = i >> 5, p = i & 31;
        sme2[p][s] = (unsigned long long)g_mask_e[s][2 * p] |
                     ((unsigned long long)g_mask_e[s][2 * p + 1] << 32);
    }
    for (int i = threadIdx.x; i < SUB * 8; i += blockDim.x) {
        int s = i >> 3, p = i & 7;
        smi2[p][s] = (unsigned long long)g_mask_i[s][2 * p] |
                     ((unsigned long long)g_mask_i[s][2 * p + 1] << 32);
    }
    __syncthreads();

    int warp = threadIdx.x >> 5, lane = threadIdx.x & 31;
    int row = blockIdx.x * 16 + warp;
    if (row >= T_DATA) return;

    const float* re = Se + (size_t)row * E_NO;
    const float* ri = Si + (size_t)row * I_NO;
    int acc_e = 0, acc_i = 0;

#pragma unroll
    for (int ob = 0; ob < 2; ob++) {
        float4 v[8];
#pragma unroll
        for (int q = 0; q < 8; q++) {
            int base = (ob * 8 + q) * 128 + lane * 4;
            v[q] = (base < E_NO) ? *(const float4*)(re + base)
                                 : make_float4(0.f, 0.f, 0.f, 0.f);
        }
#pragma unroll
        for (int q = 0; q < 8; q++) {
            int it = ob * 8 + q;
            unsigned m0 = __ballot_sync(0xffffffffu, v[q].x != 0.f);
            unsigned m1 = __ballot_sync(0xffffffffu, v[q].y != 0.f);
            unsigned m2 = __ballot_sync(0xffffffffu, v[q].z != 0.f);
            unsigned m3 = __ballot_sync(0xffffffffu, v[q].w != 0.f);
            if (lane < SUB) {
                unsigned long long A = (unsigned long long)m0 | ((unsigned long long)m1 << 32);
                unsigned long long B = (unsigned long long)m2 | ((unsigned long long)m3 << 32);
                acc_e += __popcll(A & sme2[it * 2 + 0][lane]);
                acc_e += __popcll(B & sme2[it * 2 + 1][lane]);
            }
        }
    }
    {
        float4 v[4];
#pragma unroll
        for (int q = 0; q < 4; q++) {
            int base = q * 128 + lane * 4;
            v[q] = (base < I_NO) ? *(const float4*)(ri + base)
                                 : make_float4(0.f, 0.f, 0.f, 0.f);
        }
#pragma unroll
        for (int q = 0; q < 4; q++) {
            unsigned m0 = __ballot_sync(0xffffffffu, v[q].x != 0.f);
            unsigned m1 = __ballot_sync(0xffffffffu, v[q].y != 0.f);
            unsigned m2 = __ballot_sync(0xffffffffu, v[q].z != 0.f);
            unsigned m3 = __ballot_sync(0xffffffffu, v[q].w != 0.f);
            if (lane < SUB) {
                unsigned long long A = (unsigned long long)m0 | ((unsigned long long)m1 << 32);
                unsigned long long B = (unsigned long long)m2 | ((unsigned long long)m3 << 32);
                acc_i += __popcll(A & smi2[q * 2 + 0][lane]);
                acc_i += __popcll(B & smi2[q * 2 + 1][lane]);
            }
        }
    }
    if (lane < SUB) {
        g_INe[lane][row] = (float)acc_e;
        g_INi[lane][row] = (float)acc_i;
    }
}

// ---------------- K2: fused conv(40 taps) + wavefront recurrence, TT=80 ------------
__global__ __launch_bounds__(288) void k_fused(const float* __restrict__ Ws_syn,
                                               const float* __restrict__ Wns_syn,
                                               const float* __restrict__ Ds,
                                               const float* __restrict__ Dns,
                                               const float* __restrict__ C_den,
                                               const float* __restrict__ Ths_g,
                                               const float* __restrict__ Thns_g,
                                               const float* __restrict__ Ws_g,
                                               const float* __restrict__ Wns_g,
                                               float* __restrict__ out) {
    __shared__ float ker[SUB][4][CTAP];                  // [s][e_s,i_s,e_ns,i_ns][m]
    __shared__ __align__(16) float inbe[SUB][INLEN];
    __shared__ __align__(16) float inbi[SUB][INLEN];
    __shared__ float shs[SUB][SYNLEN], shn[SUB][SYNLEN];
    __shared__ float cw[SUB][SUB], cd[SUB][SUB];
    __shared__ float ths[SUB], thn[SUB], wsb[SUB], wnb[SUB];

    const int tid = threadIdx.x;
    const int warp = tid >> 5, lane = tid & 31;
    const int t0 = blockIdx.x * TT;

    // kernel coefficients: 12*4*40 = 1920 entries
    for (int id = tid; id < SUB * 4 * CTAP; id += 288) {
        int s = id / (4 * CTAP), rem = id % (4 * CTAP);
        int c = rem / CTAP, m = rem % CTAP;
        int ch = c & 1;
        const float* W = (c >= 2) ? Wns_syn : Ws_syn;
        const float* D = (c >= 2) ? Dns : Ds;
        float fk = (float)(CTAP - 1 - m);                // reversed: index m = lag CTAP-1-m
        float u = fmaxf(fk - expf(D[s * 2 + ch]), 0.f);
        float a = u, b = u * 0.60653065971f, cc = u * 0.36787944117f;
        ker[s][c][m] = W[s * 6 + ch] * a * expf(-a) + W[s * 6 + 2 + ch] * b * expf(-b) +
                       W[s * 6 + 4 + ch] * cc * expf(-cc);
    }
    if (tid < SUB * SUB) {
        float c = C_den[tid];
        cd[tid / SUB][tid % SUB] = c;
        cw[tid / SUB][tid % SUB] = c * Wns_g[tid % SUB];
    }
    if (tid < SUB) {
        ths[tid] = Ths_g[tid];
        thn[tid] = Thns_g[tid];
        wsb[tid] = Ws_g[tid];
        wnb[tid] = Wns_g[tid];
    }
    // stage IN: i in [0,144) -> t = t0 - 52 + i (zero-fill OOB and pad)
    for (int i = tid; i < SUB * INLEN; i += 288) {
        int s = i / INLEN, ii = i % INLEN;
        int g = t0 - 52 + ii;
        bool in = (g >= 0 && g < T_DATA && ii < 136);
        inbe[s][ii] = in ? g_INe[s][g] : 0.f;
        inbi[s][ii] = in ? g_INi[s][g] : 0.f;
    }
    __syncthreads();

    // conv: 288 threads = 12 subs x 24 groups of 4 outputs; syn[j] = sum_m ker[m]*IN[j+m]
    {
        int s = tid / 24, g = tid % 24;
        const float4* re4 = (const float4*)inbe[s];
        const float4* ri4 = (const float4*)inbi[s];
        const float* kes = ker[s][0];
        const float* kis = ker[s][1];
        const float* ken = ker[s][2];
        const float* kin = ker[s][3];

        float accs[4] = {0, 0, 0, 0}, accn[4] = {0, 0, 0, 0};
        float4 Ae = re4[g], Be = re4[g + 1];
        float4 Ai = ri4[g], Bi = ri4[g + 1];
#pragma unroll
        for (int kb = 0; kb < CTAP; kb += 4) {
            float4 Ce4 = re4[g + kb / 4 + 2];
            float4 Ci4 = ri4[g + kb / 4 + 2];
            float we[8] = {Ae.x, Ae.y, Ae.z, Ae.w, Be.x, Be.y, Be.z, Be.w};
            float wi[8] = {Ai.x, Ai.y, Ai.z, Ai.w, Bi.x, Bi.y, Bi.z, Bi.w};
#pragma unroll
            for (int u = 0; u < 4; u++) {
                float c0 = kes[kb + u], c1 = kis[kb + u];
                float c2 = ken[kb + u], c3 = kin[kb + u];
#pragma unroll
                for (int r = 0; r < 4; r++) {
                    float e = we[u + r], i2 = wi[u + r];
                    accs[r] = fmaf(c0, e, accs[r]);
                    accs[r] = fmaf(c1, i2, accs[r]);
                    accn[r] = fmaf(c2, e, accn[r]);
                    accn[r] = fmaf(c3, i2, accn[r]);
                }
            }
            Ae = Be; Be = Ce4; Ai = Bi; Bi = Ci4;
        }
        int j0 = g * 4;
#pragma unroll
        for (int r = 0; r < 4; r++) {
            shs[s][j0 + r] = accs[r];
            shn[s][j0 + r] = accn[r];
        }
    }
    __syncthreads();

    // recurrence: warps 0..3 cover 80 outputs (20 each, 12-lane halo)
    if (warp < 4) {
        const int t = t0 + warp * 20 + lane - 12;
        const int j = warp * 20 + lane + 1;
        const bool tin = (t >= 0);
        const bool rec = (t >= 1);

        float sn[SUB], ss[SUB];
#pragma unroll
        for (int q = 0; q < SUB; q++) {
            sn[q] = tin ? shn[q][j] : 0.f;
            ss[q] = tin ? shs[q][j] : 0.f;
        }
        float ssp0 = rec ? shs[0][j - 1] : 0.f;

        float sig[SUB], sigp[SUB];
#pragma unroll
        for (int q = 0; q < SUB; q++) {
            float r = 0.f;
#pragma unroll
            for (int qq = 0; qq < q; qq++) r += cw[q][qq] * sigp[qq];
            float x = sn[q] + thn[q] + (rec ? r : 0.f);
            sig[q] = sigm(x);
            sigp[q] = __shfl_up_sync(0xffffffffu, sig[q], 1);
        }

        if (lane >= 12 && t < T_DATA) {
            float* o = out + (size_t)t * (3 * SUB - 1);
            o[0] = sigm(ss[0] + ths[0]) * wsb[0];
#pragma unroll
            for (int q = 1; q < SUB; q++) o[q] = sig[q] * wsb[q];
#pragma unroll
            for (int q = 0; q < SUB; q++) o[SUB + q] = sig[q] * wnb[q];

            float ysp[SUB];
            ysp[0] = rec ? sigm(ssp0 + ths[0]) * wsb[0] : 0.f;
#pragma unroll
            for (int q = 1; q < SUB; q++) ysp[q] = rec ? sigp[q] * wsb[q] : 0.f;
#pragma unroll
            for (int i = 1; i < SUB; i++) {
                float x = ss[i] + ths[i];
#pragma unroll
                for (int qq = 0; qq < i; qq++) x = fmaf(cd[i][qq], ysp[qq], x);
                o[2 * SUB + (i - 1)] = sigm(x);
            }
        }
    }
}

// ---------------- launcher ----------------
extern "C" void kernel_launch(void* const* d_in, const int* in_sizes, int n_in,
                              void* d_out, int out_size) {
    const float* S_e      = (const float*)d_in[0];
    const float* S_i      = (const float*)d_in[1];
    const float* C_syn_e  = (const float*)d_in[2];
    const float* C_syn_i  = (const float*)d_in[3];
    const float* C_den    = (const float*)d_in[4];
    const float* W_s_syn  = (const float*)d_in[5];
    const float* W_ns_syn = (const float*)d_in[6];
    const float* Delta_s  = (const float*)d_in[7];
    const float* Delta_ns = (const float*)d_in[8];
    const float* Theta_s  = (const float*)d_in[9];
    const float* Theta_ns = (const float*)d_in[10];
    const float* W_s_sub  = (const float*)d_in[11];
    const float* W_ns_sub = (const float*)d_in[12];
    float* out = (float*)d_out;

    k_pack<<<60, 128>>>(C_syn_e, C_syn_i);
    k_reduce<<<1250, 512>>>(S_e, S_i);
    k_fused<<<250, 288>>>(W_s_syn, W_ns_syn, Delta_s, Delta_ns,
                          C_den, Theta_s, Theta_ns, W_s_sub, W_ns_sub, out);
}